// round 14
// baseline (speedup 1.0000x reference)
#include <cuda_runtime.h>
#include <cstdint>

// Patcher: x (8,3,1024,1024) fp32, patch=24, stride=16, reflect pad m=4.
// out[((b*64+ph)*64+pw)*1728 + (i*24+j)*3 + c] = x[b,c,ry,rx]
//   ry=reflect(ph*16+i-4), rx=reflect(pw*16+j-4); reflect: q<0->-q, q>1023->2046-q.
//
// Persistent software-pipelined version of the 8-patch smem kernel:
//   per tile iteration: issue next tile's 6x LDG.128 -> drain current tile's
//   phase-2 (LDS.128+STG.128, wavefront-floor) -> transpose+STS next tile ->
//   one __syncthreads -> swap buffers. Load latency hides behind store drain.
// 296 persistent CTAs (2/SM), 512 thr, 78.3 KB dynamic smem (double buffer).

static constexpr unsigned HWu = 1024u * 1024u;
static constexpr long long TOTAL_ELEMS = 56623104LL;
static constexpr unsigned ROW_F4 = 102u;              // 136*3/4 f4 per tile row
static constexpr unsigned SMEM_F4 = 24u * ROW_F4;     // 2448 f4 = 39168 B / buf
static constexpr unsigned N_GROUPS = 24u * 34u;       // 816 (r,xg) groups
static constexpr unsigned N_OUT4 = 8u * 432u;         // 3456 f4 per tile
static constexpr unsigned N_TILES = 4096u;            // (b,ph,pg)
static constexpr unsigned GRID = 296u;                // 2 CTAs x 148 SMs
static constexpr unsigned SMEM_BYTES = SMEM_F4 * 2u * 16u;  // 78336

__device__ __forceinline__ int reflect_idx(int q) {
    q = (q < 0) ? -q : q;
    q = (q > 1023) ? (2046 - q) : q;
    return q;
}

__device__ __forceinline__ void load_group(const float* __restrict__ xb,
                                           int ybase, int gx0, unsigned idx,
                                           float4& a0, float4& a1, float4& a2) {
    unsigned r  = idx / 34u;
    unsigned xg = idx - r * 34u;
    int y  = reflect_idx(ybase + (int)r);
    int gx = gx0 + (int)(xg << 2);
    const float* p = xb + (unsigned)y * 1024u;
    if (gx >= 0 && gx <= 1020) {
        a0 = *reinterpret_cast<const float4*>(p + gx);
        a1 = *reinterpret_cast<const float4*>(p + HWu + gx);
        a2 = *reinterpret_cast<const float4*>(p + 2u * HWu + gx);
    } else {
        int x0 = reflect_idx(gx), x1 = reflect_idx(gx + 1);
        int x2 = reflect_idx(gx + 2), x3 = reflect_idx(gx + 3);
        a0.x = p[x0]; a0.y = p[x1]; a0.z = p[x2]; a0.w = p[x3];
        const float* q1 = p + HWu;
        a1.x = q1[x0]; a1.y = q1[x1]; a1.z = q1[x2]; a1.w = q1[x3];
        const float* q2 = p + 2u * HWu;
        a2.x = q2[x0]; a2.y = q2[x1]; a2.z = q2[x2]; a2.w = q2[x3];
    }
}

__device__ __forceinline__ void store_group(float4* __restrict__ buf,
                                            unsigned idx,
                                            float4 a0, float4 a1, float4 a2) {
    unsigned r  = idx / 34u;
    unsigned xg = idx - r * 34u;
    unsigned sbase = r * ROW_F4 + xg * 3u;
    float4 t0, t1, t2;
    t0.x = a0.x; t0.y = a1.x; t0.z = a2.x; t0.w = a0.y;
    t1.x = a1.y; t1.y = a2.y; t1.z = a0.z; t1.w = a1.z;
    t2.x = a2.z; t2.y = a0.w; t2.z = a1.w; t2.w = a2.w;
    buf[sbase + 0] = t0;
    buf[sbase + 1] = t1;
    buf[sbase + 2] = t2;
}

__global__ void __launch_bounds__(512, 2)
patcher_kernel(const float* __restrict__ x, float* __restrict__ out,
               unsigned out_size) {
    extern __shared__ float4 sm[];   // two buffers of SMEM_F4

    unsigned bid = blockIdx.x;
    unsigned tid = threadIdx.x;

    if (bid == 0 && tid < 32u) {     // tail fill: flattened (nH,nW)=(64,64)
        unsigned idx = (unsigned)TOTAL_ELEMS + tid;
        if (idx < out_size) out[idx] = 64.0f;
    }

    unsigned idx0 = tid;             // < 816 always (512 thr)
    unsigned idx1 = tid + 512u;      // valid iff tid < 304
    bool has1 = idx1 < N_GROUPS;

    // ---- prologue: stage first tile into buffer 0 ----
    unsigned t = bid;
    {
        unsigned pg = t & 7u, ph = (t >> 3) & 63u, b = t >> 9;
        const float* xb = x + (size_t)b * (3u * HWu);
        int ybase = (int)(ph << 4) - 4;
        int gx0   = (int)(pg << 7) - 4;
        float4 a0, a1, a2, b0, b1, b2;
        load_group(xb, ybase, gx0, idx0, a0, a1, a2);
        if (has1) load_group(xb, ybase, gx0, idx1, b0, b1, b2);
        store_group(sm, idx0, a0, a1, a2);
        if (has1) store_group(sm, idx1, b0, b1, b2);
    }
    __syncthreads();

    unsigned p = 0;
    while (t < N_TILES) {
        unsigned tn = t + GRID;
        bool hasnext = tn < N_TILES;

        // 1) issue next tile's loads (latency overlaps phase-2 below)
        float4 a0, a1, a2, b0, b1, b2;
        if (hasnext) {
            unsigned pg = tn & 7u, ph = (tn >> 3) & 63u, b = tn >> 9;
            const float* xb = x + (size_t)b * (3u * HWu);
            int ybase = (int)(ph << 4) - 4;
            int gx0   = (int)(pg << 7) - 4;
            load_group(xb, ybase, gx0, idx0, a0, a1, a2);
            if (has1) load_group(xb, ybase, gx0, idx1, b0, b1, b2);
        }

        // 2) phase-2 drain of current tile from buffer p
        {
            unsigned pg = t & 7u, ph = (t >> 3) & 63u, b = t >> 9;
            unsigned patch0 = (b << 12) + (ph << 6) + (pg << 3);
            float4* o4 = reinterpret_cast<float4*>(out) + (size_t)patch0 * 432u;
            const float4* buf = sm + p * SMEM_F4;
            #pragma unroll
            for (unsigned it = 0; it < 7; ++it) {
                unsigned idx = tid + it * 512u;
                if (idx < N_OUT4) {
                    unsigned pl  = idx / 432u;
                    unsigned rem = idx - pl * 432u;
                    unsigned i   = rem / 18u;
                    unsigned off = rem - i * 18u;
                    o4[idx] = buf[i * ROW_F4 + pl * 12u + off];
                }
            }
        }

        // 3) transpose + STS next tile into the other buffer
        if (hasnext) {
            float4* nbuf = sm + (p ^ 1u) * SMEM_F4;
            store_group(nbuf, idx0, a0, a1, a2);
            if (has1) store_group(nbuf, idx1, b0, b1, b2);
        }
        __syncthreads();
        p ^= 1u;
        t = tn;
    }
}

extern "C" void kernel_launch(void* const* d_in, const int* in_sizes, int n_in,
                              void* d_out, int out_size) {
    const float* x = (const float*)d_in[0];
    float* out = (float*)d_out;
    cudaFuncSetAttribute(patcher_kernel,
                         cudaFuncAttributeMaxDynamicSharedMemorySize,
                         SMEM_BYTES);
    patcher_kernel<<<GRID, 512, SMEM_BYTES>>>(x, out, (unsigned)out_size);
}

// round 15
// speedup vs baseline: 1.0517x; 1.0517x over previous
#include <cuda_runtime.h>
#include <cstdint>

// Patcher: x (8,3,1024,1024) fp32, patch=24, stride=16, reflect pad m=4.
// out[((b*64+ph)*64+pw)*1728 + (i*24+j)*3 + c] = x[b,c,ry,rx]
//   ry=reflect(ph*16+i-4), rx=reflect(pw*16+j-4); reflect: q<0->-q, q>1023->2046-q.
//
// Champion structure (R6/R8): block (512 thr) = (b, ph, pg), 8 patches.
// smem tile s[r][x][c], c-fastest (= output order), 136 cols.
//   Phase 1: 3x LDG.128 (channel planes) -> in-lane transpose -> 3x STS.128.
//   Phase 2: LDS.128 + STG.128, lane-consecutive (wavefront floor),
//            incremental index decode.
// 4 CTAs/SM x 16 warps = 64 warps = full occupancy; 39.2 KB smem; regs ~32.
// bid swizzle: consecutive bids form 2(ph) x 4(pg) super-tiles for L2 read
// locality in both dimensions.

static constexpr unsigned HWu = 1024u * 1024u;
static constexpr long long TOTAL_ELEMS = 56623104LL;
static constexpr unsigned ROW_F4 = 102u;              // 136*3/4 float4 per smem row
static constexpr unsigned SMEM_F4 = 24u * ROW_F4;     // 2448 float4 = 39168 B
static constexpr unsigned N_GROUPS = 24u * 34u;       // (r, xg) groups = 816
static constexpr unsigned N_OUT4 = 8u * 432u;         // 3456 float4 per block

__device__ __forceinline__ int reflect_idx(int q) {
    q = (q < 0) ? -q : q;
    q = (q > 1023) ? (2046 - q) : q;
    return q;
}

__global__ void __launch_bounds__(512, 4)
patcher_kernel(const float* __restrict__ x, float* __restrict__ out,
               unsigned out_size) {
    __shared__ float4 s4[SMEM_F4];

    unsigned bid = blockIdx.x;
    unsigned tid = threadIdx.x;

    // 2D-local swizzle: bid -> (b, ph, pg) with 2x4 (ph x pg) super-tiles.
    // bid bits: [2:0] = (phl, pgl(2)), [8:3] = super index, [11:9] = b
    unsigned pgl = bid & 3u;               // pg low 2 bits
    unsigned phl = (bid >> 2) & 1u;        // ph low bit
    unsigned sup = (bid >> 3) & 63u;       // 64 super-tiles per b (32 ph-pairs x 2 pg-pairs)
    unsigned b   = bid >> 9;
    unsigned pg  = ((sup & 1u) << 2) | pgl;        // pg = 2*sup_lo*2 + pgl -> 0..7
    unsigned ph  = ((sup >> 1) << 1) | phl;        // ph = sup_hi*2 + phl -> 0..63

    if (bid == 0 && tid < 32u) {     // tail fill: flattened (nH,nW)=(64,64)
        unsigned idx = (unsigned)TOTAL_ELEMS + tid;
        if (idx < out_size) out[idx] = 64.0f;
    }

    // ---- Phase 1: stage + in-lane transpose ----
    const float* xb = x + (size_t)b * (3u * HWu);
    int ybase = (int)(ph << 4) - 4;
    int gx0   = (int)(pg << 7) - 4;   // tile x origin (pg*128 - 4)

    #pragma unroll
    for (unsigned it = 0; it < 2; ++it) {
        unsigned idx = tid + it * 512u;
        if (idx < N_GROUPS) {
            unsigned r  = idx / 34u;
            unsigned xg = idx - r * 34u;
            int y  = reflect_idx(ybase + (int)r);
            int gx = gx0 + (int)(xg << 2);

            const float* p = xb + (unsigned)y * 1024u;
            float4 a0, a1, a2;
            if (gx >= 0 && gx <= 1020) {
                a0 = *reinterpret_cast<const float4*>(p + gx);
                a1 = *reinterpret_cast<const float4*>(p + HWu + gx);
                a2 = *reinterpret_cast<const float4*>(p + 2u * HWu + gx);
            } else {
                int x0 = reflect_idx(gx), x1 = reflect_idx(gx + 1);
                int x2 = reflect_idx(gx + 2), x3 = reflect_idx(gx + 3);
                a0.x = p[x0]; a0.y = p[x1]; a0.z = p[x2]; a0.w = p[x3];
                const float* q1 = p + HWu;
                a1.x = q1[x0]; a1.y = q1[x1]; a1.z = q1[x2]; a1.w = q1[x3];
                const float* q2 = p + 2u * HWu;
                a2.x = q2[x0]; a2.y = q2[x1]; a2.z = q2[x2]; a2.w = q2[x3];
            }
            // transpose to c-fastest
            unsigned sbase = r * ROW_F4 + xg * 3u;
            float4 t0, t1, t2;
            t0.x = a0.x; t0.y = a1.x; t0.z = a2.x; t0.w = a0.y;
            t1.x = a1.y; t1.y = a2.y; t1.z = a0.z; t1.w = a1.z;
            t2.x = a2.z; t2.y = a0.w; t2.z = a1.w; t2.w = a2.w;
            s4[sbase + 0] = t0;
            s4[sbase + 1] = t1;
            s4[sbase + 2] = t2;
        }
    }
    __syncthreads();

    // ---- Phase 2: coalesced copy out, incremental decode ----
    unsigned patch0 = (b << 12) + (ph << 6) + (pg << 3);
    float4* o4 = reinterpret_cast<float4*>(out) + (size_t)patch0 * 432u;

    unsigned idx = tid;
    unsigned pl  = idx / 432u;
    unsigned rem = idx - pl * 432u;
    unsigned i   = rem / 18u;
    unsigned off = rem - i * 18u;

    #pragma unroll
    for (unsigned it = 0; it < 7; ++it) {
        if (idx < N_OUT4) {
            o4[idx] = s4[i * ROW_F4 + pl * 12u + off];
        }
        // advance by 512 = 1 patch (432) + 4 rows (72) + 8 f4
        idx += 512u;
        pl  += 1u;
        i   += 4u;
        off += 8u;
        if (off >= 18u) { off -= 18u; i += 1u; }
        if (i >= 24u)   { i -= 24u; pl += 1u; }
    }
}

extern "C" void kernel_launch(void* const* d_in, const int* in_sizes, int n_in,
                              void* d_out, int out_size) {
    const float* x = (const float*)d_in[0];
    float* out = (float*)d_out;
    patcher_kernel<<<4096, 512>>>(x, out, (unsigned)out_size);
}